// round 4
// baseline (speedup 1.0000x reference)
#include <cuda_runtime.h>
#include <cuda_bf16.h>
#include <cstdint>
#include <cstddef>

#define NN   8192
#define HID  192
#define INF  256
#define MAXN 128

// ---------------- device scratch ----------------
__device__ float g_support[NN * HID];
__device__ float g_featbuf[NN * HID];
__device__ float g_xbuf[NN * HID];
__device__ __nv_bfloat16 g_xhi[NN * INF];
__device__ __nv_bfloat16 g_xlo[NN * INF];
#define WT_TOTAL (192*256 + 12*192*192)
__device__ __nv_bfloat16 g_wthi[WT_TOTAL];
__device__ __nv_bfloat16 g_wtlo[WT_TOTAL];
__device__ int   g_nidx[NN * MAXN];
__device__ float g_nval[NN * MAXN];
__device__ int   g_ncnt[NN];

// ---------------- PTX helpers (compute_103-safe) ----------------
__device__ __forceinline__ uint32_t smem_u32(const void* p) {
    uint32_t a;
    asm("{ .reg .u64 t; cvta.to.shared.u64 t, %1; cvt.u32.u64 %0, t; }" : "=r"(a) : "l"(p));
    return a;
}
__device__ __forceinline__ void cp16(uint32_t d, const void* s) {
    asm volatile("cp.async.cg.shared.global [%0], [%1], 16;" :: "r"(d), "l"(s));
}
__device__ __forceinline__ void cp_commit() {
    asm volatile("cp.async.commit_group;" ::: "memory");
}
template <int N> __device__ __forceinline__ void cp_wait() {
    asm volatile("cp.async.wait_group %0;" :: "n"(N) : "memory");
}
__device__ __forceinline__ void ldmx4(uint32_t* r, uint32_t a) {
    asm volatile("ldmatrix.sync.aligned.m8n8.x4.shared.b16 {%0,%1,%2,%3}, [%4];"
        : "=r"(r[0]), "=r"(r[1]), "=r"(r[2]), "=r"(r[3]) : "r"(a));
}
__device__ __forceinline__ void mma16816(float* d, const uint32_t* a, const uint32_t* b) {
    asm volatile("mma.sync.aligned.m16n8k16.row.col.f32.bf16.bf16.f32 "
        "{%0,%1,%2,%3}, {%4,%5,%6,%7}, {%8,%9}, {%0,%1,%2,%3};"
        : "+f"(d[0]), "+f"(d[1]), "+f"(d[2]), "+f"(d[3])
        : "r"(a[0]), "r"(a[1]), "r"(a[2]), "r"(a[3]), "r"(b[0]), "r"(b[1]));
}

// ---------------- CSR extraction ----------------
__global__ __launch_bounds__(256) void build_csr(const float* __restrict__ adj,
                                                 int* __restrict__ nidx,
                                                 float* __restrict__ nval,
                                                 int* __restrict__ ncnt)
{
    int warp = (blockIdx.x * blockDim.x + threadIdx.x) >> 5;
    int lane = threadIdx.x & 31;
    if (warp >= NN) return;
    const float4* row = reinterpret_cast<const float4*>(adj + (size_t)warp * NN);
    int* my_idx = nidx + (size_t)warp * MAXN;
    float* my_val = nval + (size_t)warp * MAXN;
    int count = 0;
    for (int it = 0; it < NN / 128; it++) {
        float4 v = row[it * 32 + lane];
        int c0 = it * 128 + lane * 4;
        int my = (v.x != 0.f) + (v.y != 0.f) + (v.z != 0.f) + (v.w != 0.f);
        int inc = my;
        #pragma unroll
        for (int d = 1; d < 32; d <<= 1) {
            int t = __shfl_up_sync(0xffffffffu, inc, d);
            if (lane >= d) inc += t;
        }
        int total = __shfl_sync(0xffffffffu, inc, 31);
        int pos = count + inc - my;
        if (v.x != 0.f) { if (pos < MAXN) { my_idx[pos] = c0;     my_val[pos] = v.x; } pos++; }
        if (v.y != 0.f) { if (pos < MAXN) { my_idx[pos] = c0 + 1; my_val[pos] = v.y; } pos++; }
        if (v.z != 0.f) { if (pos < MAXN) { my_idx[pos] = c0 + 2; my_val[pos] = v.z; } pos++; }
        if (v.w != 0.f) { if (pos < MAXN) { my_idx[pos] = c0 + 3; my_val[pos] = v.w; } pos++; }
        count += total;
    }
    if (lane == 0) ncnt[warp] = count > MAXN ? MAXN : count;
}

// ---------------- weight / feature conversion ----------------
__global__ __launch_bounds__(256) void convert_weights(const float* __restrict__ W1,
                                                       const float* __restrict__ W_mid,
                                                       __nv_bfloat16* __restrict__ whi,
                                                       __nv_bfloat16* __restrict__ wlo)
{
    int idx = blockIdx.x * blockDim.x + threadIdx.x;
    if (idx >= WT_TOTAL) return;
    float w;
    if (idx < 192 * 256) {
        int n = idx / 256, k = idx % 256;
        w = W1[k * 192 + n];
    } else {
        int rel = idx - 192 * 256;
        int i = rel / (192 * 192);
        int r = rel % (192 * 192);
        int n = r / 192, k = r % 192;
        w = W_mid[(size_t)i * 192 * 192 + k * 192 + n];
    }
    __nv_bfloat16 h = __float2bfloat16(w);
    whi[idx] = h;
    wlo[idx] = __float2bfloat16(w - __bfloat162float(h));
}

__global__ __launch_bounds__(256) void convert_features(const float* __restrict__ f,
                                                        __nv_bfloat16* __restrict__ xhi,
                                                        __nv_bfloat16* __restrict__ xlo)
{
    int idx = blockIdx.x * blockDim.x + threadIdx.x;
    if (idx >= NN * INF) return;
    float v = f[idx];
    __nv_bfloat16 h = __float2bfloat16(v);
    xhi[idx] = h;
    xlo[idx] = __float2bfloat16(v - __bfloat162float(h));
}

// ---------------- split-bf16 HMMA GEMM: S[8192,192] = X[8192,K] @ Wt^T ----
// BM=64, BN=64, BK=32, 256 thr / 8 warps (4m x 2n), warp tile 16x32.
// 3-stage cp.async ring, one __syncthreads per chunk.
#define BM 64
#define BN 64
#define BK 32
#define ASTR 80
#define SA_H 0
#define SA_L (BM * ASTR)                 // 5120
#define SB_H (2 * BM * ASTR)             // 10240
#define SB_L (2 * BM * ASTR + BN * ASTR) // 15360
#define STAGE_BYTES (2 * BM * ASTR + 2 * BN * ASTR)  // 20480
#define NSTAGE 3
#define GEMM_SMEM (NSTAGE * STAGE_BYTES)             // 61440

__global__ void __launch_bounds__(256, 2)
gemm_mma(const __nv_bfloat16* __restrict__ Xh, const __nv_bfloat16* __restrict__ Xl,
         const __nv_bfloat16* __restrict__ Wh, const __nv_bfloat16* __restrict__ Wl,
         float* __restrict__ S, int K)
{
    extern __shared__ char smem[];
    uint32_t sb = smem_u32(smem);
    int tid = threadIdx.x;
    int m0 = blockIdx.x * BM;
    int n0 = blockIdx.y * BN;
    int w = tid >> 5, lane = tid & 31;
    int wm = (w & 3) * 16;
    int wn = (w >> 2) * 32;

    float acc[4][4];
    #pragma unroll
    for (int nt = 0; nt < 4; nt++)
        #pragma unroll
        for (int q = 0; q < 4; q++) acc[nt][q] = 0.f;

    int nch = K / BK;
    int arow_ld = tid >> 2, aseg = tid & 3;   // 64 rows x 4 segs, one per thread

    auto issue_load = [&](int c, int stg) {
        uint32_t base = sb + stg * STAGE_BYTES;
        int k0 = c * BK;
        size_t ga = (size_t)(m0 + arow_ld) * K + k0 + aseg * 8;
        size_t gb = (size_t)(n0 + arow_ld) * K + k0 + aseg * 8;
        uint32_t so = arow_ld * ASTR + aseg * 16;
        cp16(base + SA_H + so, Xh + ga);
        cp16(base + SA_L + so, Xl + ga);
        cp16(base + SB_H + so, Wh + gb);
        cp16(base + SB_L + so, Wl + gb);
    };

    auto compute = [&](int stg) {
        uint32_t base = sb + stg * STAGE_BYTES;
        #pragma unroll
        for (int ks = 0; ks < 2; ks++) {
            uint32_t ah[4], al[4], bh[2][4], bl[2][4];
            {
                uint32_t arow = wm + (lane & 15);
                uint32_t aoff = base + arow * ASTR + ks * 32 + (lane >> 4) * 16;
                ldmx4(ah, aoff + SA_H);
                ldmx4(al, aoff + SA_L);
            }
            #pragma unroll
            for (int p = 0; p < 2; p++) {
                uint32_t brow = wn + p * 16 + (lane & 7) + ((lane >> 4) << 3);
                uint32_t boff = base + brow * ASTR + ks * 32 + (((lane >> 3) & 1) * 16);
                ldmx4(bh[p], boff + SB_H);
                ldmx4(bl[p], boff + SB_L);
            }
            #pragma unroll
            for (int nt = 0; nt < 4; nt++) {
                const uint32_t* b2h = &bh[nt >> 1][(nt & 1) * 2];
                const uint32_t* b2l = &bl[nt >> 1][(nt & 1) * 2];
                mma16816(acc[nt], ah, b2h);
                mma16816(acc[nt], ah, b2l);
                mma16816(acc[nt], al, b2h);
            }
        }
    };

    issue_load(0, 0); cp_commit();
    issue_load(1, 1); cp_commit();
    for (int c = 0; c < nch; c++) {
        if (c + 1 < nch) cp_wait<1>(); else cp_wait<0>();
        __syncthreads();
        if (c + 2 < nch) { issue_load(c + 2, (c + 2) % NSTAGE); cp_commit(); }
        compute(c % NSTAGE);
    }

    int rb = m0 + wm + (lane >> 2);
    int cb = n0 + wn + (lane & 3) * 2;
    #pragma unroll
    for (int nt = 0; nt < 4; nt++) {
        int cc = cb + nt * 8;
        *reinterpret_cast<float2*>(&S[(size_t)rb * HID + cc]) =
            make_float2(acc[nt][0], acc[nt][1]);
        *reinterpret_cast<float2*>(&S[(size_t)(rb + 8) * HID + cc]) =
            make_float2(acc[nt][2], acc[nt][3]);
    }
}

// ---------------- tiny GEMM for W_out (192x3) ----------------
__global__ __launch_bounds__(256) void gemm3_kernel(const float* __restrict__ X,
                                                    const float* __restrict__ W,
                                                    float* __restrict__ S)
{
    int r = blockIdx.x * blockDim.x + threadIdx.x;
    if (r >= NN) return;
    const float* x = X + (size_t)r * HID;
    float a0 = 0.f, a1 = 0.f, a2 = 0.f;
    #pragma unroll 4
    for (int k = 0; k < HID; k++) {
        float xv = x[k];
        a0 = fmaf(xv, W[k * 3 + 0], a0);
        a1 = fmaf(xv, W[k * 3 + 1], a1);
        a2 = fmaf(xv, W[k * 3 + 2], a2);
    }
    S[r * 3 + 0] = a0; S[r * 3 + 1] = a1; S[r * 3 + 2] = a2;
}

// ---------------- fused aggregation + bias + relu + residual + bf16-split ----
__global__ __launch_bounds__(256) void agg_kernel(const float* __restrict__ S,
                                                  const float* __restrict__ bias,
                                                  const float* __restrict__ res, int res_stride,
                                                  float* __restrict__ out,
                                                  float* __restrict__ out2,
                                                  __nv_bfloat16* __restrict__ ohi,
                                                  __nv_bfloat16* __restrict__ olo,
                                                  const int* __restrict__ nidx,
                                                  const float* __restrict__ nval,
                                                  const int* __restrict__ ncnt,
                                                  int n_out, int side, int do_relu)
{
    int warp = (blockIdx.x * blockDim.x + threadIdx.x) >> 5;
    int lane = threadIdx.x & 31;
    if (warp >= NN) return;
    int cnt = ncnt[warp];
    const int* ni = nidx + (size_t)warp * MAXN;
    const float* nv = nval + (size_t)warp * MAXN;
    float acc0 = 0.f, acc1 = 0.f;
    if (side > 32) {
        float e0 = 0.f, e1 = 0.f;   // second accumulator pair to break FMA chain
        int i = 0;
        for (; i + 4 <= cnt; i += 4) {
            int   i0 = ni[i],     i1 = ni[i + 1], i2 = ni[i + 2], i3 = ni[i + 3];
            float v0 = nv[i],     v1 = nv[i + 1], v2 = nv[i + 2], v3 = nv[i + 3];
            const float* s0 = S + (size_t)i0 * n_out;
            const float* s1 = S + (size_t)i1 * n_out;
            const float* s2 = S + (size_t)i2 * n_out;
            const float* s3 = S + (size_t)i3 * n_out;
            acc0 = fmaf(v0, s0[lane], acc0);      acc1 = fmaf(v0, s0[lane + 32], acc1);
            e0   = fmaf(v1, s1[lane], e0);        e1   = fmaf(v1, s1[lane + 32], e1);
            acc0 = fmaf(v2, s2[lane], acc0);      acc1 = fmaf(v2, s2[lane + 32], acc1);
            e0   = fmaf(v3, s3[lane], e0);        e1   = fmaf(v3, s3[lane + 32], e1);
        }
        for (; i < cnt; i++) {
            const float* sr = S + (size_t)ni[i] * n_out;
            float v = nv[i];
            acc0 = fmaf(v, sr[lane], acc0);
            acc1 = fmaf(v, sr[lane + 32], acc1);
        }
        acc0 += e0; acc1 += e1;
    } else {
        for (int i = 0; i < cnt; i++) {
            if (lane < side) acc0 = fmaf(nv[i], S[(size_t)ni[i] * n_out + lane], acc0);
        }
    }
    int nj = (n_out + 31) >> 5;
    for (int j = 0; j < nj; j++) {
        int c = 32 * j + lane;
        if (c < n_out) {
            float t = (c < side) ? (j == 0 ? acc0 : acc1)
                                 : S[(size_t)warp * n_out + c];
            t += bias[c];
            if (do_relu) t = fmaxf(t, 0.f);
            if (res) t = (res[(size_t)warp * res_stride + c] + t) * 0.5f;
            size_t idx = (size_t)warp * n_out + c;
            out[idx] = t;
            if (out2) out2[idx] = t;
            if (ohi) {
                __nv_bfloat16 h = __float2bfloat16(t);
                ohi[idx] = h;
                olo[idx] = __float2bfloat16(t - __bfloat162float(h));
            }
        }
    }
}

extern "C" void kernel_launch(void* const* d_in, const int* in_sizes, int n_in,
                              void* d_out, int out_size)
{
    const float* features = (const float*)d_in[0];
    const float* adj      = (const float*)d_in[1];
    const float* W1       = (const float*)d_in[2];
    const float* b1       = (const float*)d_in[3];
    const float* W_mid    = (const float*)d_in[4];
    const float* b_mid    = (const float*)d_in[5];
    const float* W_out    = (const float*)d_in[6];
    const float* b_out    = (const float*)d_in[7];
    float* out = (float*)d_out;
    float* coords   = out;
    float* feat_out = out + NN * 3;

    float *sup, *fb, *xb, *nval;
    __nv_bfloat16 *xhi, *xlo, *whi, *wlo;
    int *nidx, *ncnt;
    cudaGetSymbolAddress((void**)&sup,  g_support);
    cudaGetSymbolAddress((void**)&fb,   g_featbuf);
    cudaGetSymbolAddress((void**)&xb,   g_xbuf);
    cudaGetSymbolAddress((void**)&xhi,  g_xhi);
    cudaGetSymbolAddress((void**)&xlo,  g_xlo);
    cudaGetSymbolAddress((void**)&whi,  g_wthi);
    cudaGetSymbolAddress((void**)&wlo,  g_wtlo);
    cudaGetSymbolAddress((void**)&nidx, g_nidx);
    cudaGetSymbolAddress((void**)&nval, g_nval);
    cudaGetSymbolAddress((void**)&ncnt, g_ncnt);

    cudaFuncSetAttribute(gemm_mma, cudaFuncAttributeMaxDynamicSharedMemorySize, GEMM_SMEM);

    convert_weights<<<(WT_TOTAL + 255) / 256, 256>>>(W1, W_mid, whi, wlo);
    convert_features<<<(NN * INF + 255) / 256, 256>>>(features, xhi, xlo);
    build_csr<<<NN / 8, 256>>>(adj, nidx, nval, ncnt);

    dim3 ggrid(NN / BM, HID / BN);   // 128 x 3 = 384 CTAs
    auto woff = [](int i) { return (size_t)192 * 256 + (size_t)i * 192 * 192; };

    // gc1 (K = 256)
    gemm_mma<<<ggrid, 256, GEMM_SMEM>>>(xhi, xlo, whi, wlo, sup, INF);
    agg_kernel<<<NN / 8, 256>>>(sup, b1, nullptr, 0, xb, nullptr, xhi, xlo,
                                nidx, nval, ncnt, HID, 64, 1);
    // gc2 + residual vs features[:, :192]
    gemm_mma<<<ggrid, 256, GEMM_SMEM>>>(xhi, xlo, whi + woff(0), wlo + woff(0), sup, HID);
    agg_kernel<<<NN / 8, 256>>>(sup, b_mid + 0, features, INF, fb, nullptr, xhi, xlo,
                                nidx, nval, ncnt, HID, 64, 1);

    const int pair_idx[5] = {1, 3, 5, 7, 9};
    for (int p = 0; p < 5; p++) {
        int i = pair_idx[p];
        gemm_mma<<<ggrid, 256, GEMM_SMEM>>>(xhi, xlo, whi + woff(i), wlo + woff(i), sup, HID);
        agg_kernel<<<NN / 8, 256>>>(sup, b_mid + (size_t)i * HID, nullptr, 0, xb, nullptr, xhi, xlo,
                                    nidx, nval, ncnt, HID, 64, 1);
        gemm_mma<<<ggrid, 256, GEMM_SMEM>>>(xhi, xlo, whi + woff(i + 1), wlo + woff(i + 1), sup, HID);
        agg_kernel<<<NN / 8, 256>>>(sup, b_mid + (size_t)(i + 1) * HID, fb, HID, fb, nullptr, xhi, xlo,
                                    nidx, nval, ncnt, HID, 64, 1);
    }

    // gc13 (+ residual); writes feat to output region too
    gemm_mma<<<ggrid, 256, GEMM_SMEM>>>(xhi, xlo, whi + woff(11), wlo + woff(11), sup, HID);
    agg_kernel<<<NN / 8, 256>>>(sup, b_mid + (size_t)11 * HID, fb, HID, fb, feat_out, nullptr, nullptr,
                                nidx, nval, ncnt, HID, 64, 1);

    // gc14: coords, side_len = 2, no relu
    gemm3_kernel<<<NN / 256, 256>>>(fb, W_out, sup);
    agg_kernel<<<NN / 8, 256>>>(sup, b_out, nullptr, 0, coords, nullptr, nullptr, nullptr,
                                nidx, nval, ncnt, 3, 2, 0);
}

// round 5
// speedup vs baseline: 1.0149x; 1.0149x over previous
#include <cuda_runtime.h>
#include <cuda_bf16.h>
#include <cstdint>
#include <cstddef>

#define NN   8192
#define HID  192
#define INF  256
#define MAXN 128

// ---------------- device scratch ----------------
__device__ float g_support[NN * HID];
__device__ float g_featbuf[NN * HID];
__device__ float g_xbuf[NN * HID];
__device__ __nv_bfloat16 g_xhi[NN * INF];
__device__ __nv_bfloat16 g_xlo[NN * INF];
#define WT_TOTAL (192*256 + 12*192*192)
__device__ __nv_bfloat16 g_wthi[WT_TOTAL];
__device__ __nv_bfloat16 g_wtlo[WT_TOTAL];
__device__ int   g_nidx[NN * MAXN];
__device__ float g_nval[NN * MAXN];
__device__ int   g_ncnt[NN];

// ---------------- PTX helpers (compute_103-safe) ----------------
__device__ __forceinline__ uint32_t smem_u32(const void* p) {
    uint32_t a;
    asm("{ .reg .u64 t; cvta.to.shared.u64 t, %1; cvt.u32.u64 %0, t; }" : "=r"(a) : "l"(p));
    return a;
}
__device__ __forceinline__ void cp16(uint32_t d, const void* s) {
    asm volatile("cp.async.cg.shared.global [%0], [%1], 16;" :: "r"(d), "l"(s));
}
__device__ __forceinline__ void cp_commit() {
    asm volatile("cp.async.commit_group;" ::: "memory");
}
__device__ __forceinline__ void cp_wait_all() {
    asm volatile("cp.async.wait_all;" ::: "memory");
}
__device__ __forceinline__ void ldmx4(uint32_t* r, uint32_t a) {
    asm volatile("ldmatrix.sync.aligned.m8n8.x4.shared.b16 {%0,%1,%2,%3}, [%4];"
        : "=r"(r[0]), "=r"(r[1]), "=r"(r[2]), "=r"(r[3]) : "r"(a));
}
__device__ __forceinline__ void mma16816(float* d, const uint32_t* a, const uint32_t* b) {
    asm volatile("mma.sync.aligned.m16n8k16.row.col.f32.bf16.bf16.f32 "
        "{%0,%1,%2,%3}, {%4,%5,%6,%7}, {%8,%9}, {%0,%1,%2,%3};"
        : "+f"(d[0]), "+f"(d[1]), "+f"(d[2]), "+f"(d[3])
        : "r"(a[0]), "r"(a[1]), "r"(a[2]), "r"(a[3]), "r"(b[0]), "r"(b[1]));
}

// ---------------- CSR extraction ----------------
__global__ __launch_bounds__(256) void build_csr(const float* __restrict__ adj,
                                                 int* __restrict__ nidx,
                                                 float* __restrict__ nval,
                                                 int* __restrict__ ncnt)
{
    int warp = (blockIdx.x * blockDim.x + threadIdx.x) >> 5;
    int lane = threadIdx.x & 31;
    if (warp >= NN) return;
    const float4* row = reinterpret_cast<const float4*>(adj + (size_t)warp * NN);
    int* my_idx = nidx + (size_t)warp * MAXN;
    float* my_val = nval + (size_t)warp * MAXN;
    int count = 0;
    for (int it = 0; it < NN / 128; it++) {
        float4 v = row[it * 32 + lane];
        int c0 = it * 128 + lane * 4;
        int my = (v.x != 0.f) + (v.y != 0.f) + (v.z != 0.f) + (v.w != 0.f);
        int inc = my;
        #pragma unroll
        for (int d = 1; d < 32; d <<= 1) {
            int t = __shfl_up_sync(0xffffffffu, inc, d);
            if (lane >= d) inc += t;
        }
        int total = __shfl_sync(0xffffffffu, inc, 31);
        int pos = count + inc - my;
        if (v.x != 0.f) { if (pos < MAXN) { my_idx[pos] = c0;     my_val[pos] = v.x; } pos++; }
        if (v.y != 0.f) { if (pos < MAXN) { my_idx[pos] = c0 + 1; my_val[pos] = v.y; } pos++; }
        if (v.z != 0.f) { if (pos < MAXN) { my_idx[pos] = c0 + 2; my_val[pos] = v.z; } pos++; }
        if (v.w != 0.f) { if (pos < MAXN) { my_idx[pos] = c0 + 3; my_val[pos] = v.w; } pos++; }
        count += total;
    }
    if (lane == 0) ncnt[warp] = count > MAXN ? MAXN : count;
}

// ---------------- weight / feature conversion ----------------
__global__ __launch_bounds__(256) void convert_weights(const float* __restrict__ W1,
                                                       const float* __restrict__ W_mid,
                                                       __nv_bfloat16* __restrict__ whi,
                                                       __nv_bfloat16* __restrict__ wlo)
{
    int idx = blockIdx.x * blockDim.x + threadIdx.x;
    if (idx >= WT_TOTAL) return;
    float w;
    if (idx < 192 * 256) {
        int n = idx / 256, k = idx % 256;
        w = W1[k * 192 + n];
    } else {
        int rel = idx - 192 * 256;
        int i = rel / (192 * 192);
        int r = rel % (192 * 192);
        int n = r / 192, k = r % 192;
        w = W_mid[(size_t)i * 192 * 192 + k * 192 + n];
    }
    __nv_bfloat16 h = __float2bfloat16(w);
    whi[idx] = h;
    wlo[idx] = __float2bfloat16(w - __bfloat162float(h));
}

__global__ __launch_bounds__(256) void convert_features(const float* __restrict__ f,
                                                        __nv_bfloat16* __restrict__ xhi,
                                                        __nv_bfloat16* __restrict__ xlo)
{
    int idx = blockIdx.x * blockDim.x + threadIdx.x;
    if (idx >= NN * INF) return;
    float v = f[idx];
    __nv_bfloat16 h = __float2bfloat16(v);
    xhi[idx] = h;
    xlo[idx] = __float2bfloat16(v - __bfloat162float(h));
}

// ---------------- one-shot split-bf16 HMMA GEMM ----------------
// S[8192,192] = X[8192,K] @ Wt^T.  BM=64, BN=64.
// Entire A(64xK) and B(64xK) tiles (hi+lo) loaded in ONE cp.async batch,
// one wait + one barrier, then barrier-free ldmatrix/HMMA stream.
#define BM 64
#define BN 64

template <int KK>
__global__ void __launch_bounds__(256, 1)
gemm_os(const __nv_bfloat16* __restrict__ Xh, const __nv_bfloat16* __restrict__ Xl,
        const __nv_bfloat16* __restrict__ Wh, const __nv_bfloat16* __restrict__ Wl,
        float* __restrict__ S)
{
    constexpr int ASTR = KK * 2 + 16;        // bytes/row; +16 keeps ldmatrix conflict-free
    constexpr int SLAB = BM * ASTR;
    constexpr int SEGS = KK / 8;             // 16B segments per row
    extern __shared__ char smem[];
    uint32_t sb = smem_u32(smem);
    const uint32_t sAH = sb, sAL = sb + SLAB, sBH = sb + 2 * SLAB, sBL = sb + 3 * SLAB;

    int tid = threadIdx.x;
    int m0 = blockIdx.x * BM;
    int n0 = blockIdx.y * BN;
    int w = tid >> 5, lane = tid & 31;
    int wm = (w & 3) * 16;
    int wn = (w >> 2) * 32;

    // ---- one-shot loads: 4 matrices x 64 rows x SEGS segs ----
    #pragma unroll
    for (int v = tid; v < BM * SEGS; v += 256) {
        int row = v / SEGS, seg = v % SEGS;
        uint32_t so = row * ASTR + seg * 16;
        size_t ga = (size_t)(m0 + row) * KK + seg * 8;
        size_t gb = (size_t)(n0 + row) * KK + seg * 8;
        cp16(sAH + so, Xh + ga);
        cp16(sAL + so, Xl + ga);
        cp16(sBH + so, Wh + gb);
        cp16(sBL + so, Wl + gb);
    }
    cp_commit();

    float acc[4][4];
    #pragma unroll
    for (int nt = 0; nt < 4; nt++)
        #pragma unroll
        for (int q = 0; q < 4; q++) acc[nt][q] = 0.f;

    cp_wait_all();
    __syncthreads();

    // ---- barrier-free compute: KK/16 k-steps ----
    uint32_t aoff = (wm + (lane & 15)) * ASTR + (lane >> 4) * 16;
    uint32_t boff0 = (wn + (lane & 7) + ((lane >> 4) << 3)) * ASTR + (((lane >> 3) & 1) * 16);
    uint32_t boff1 = boff0 + 16 * ASTR;

    #pragma unroll
    for (int ks = 0; ks < KK / 16; ks++) {
        uint32_t ko = ks * 32;
        uint32_t ah[4], al[4], bh[2][4], bl[2][4];
        ldmx4(ah, sAH + aoff + ko);
        ldmx4(al, sAL + aoff + ko);
        ldmx4(bh[0], sBH + boff0 + ko);
        ldmx4(bl[0], sBL + boff0 + ko);
        ldmx4(bh[1], sBH + boff1 + ko);
        ldmx4(bl[1], sBL + boff1 + ko);
        #pragma unroll
        for (int nt = 0; nt < 4; nt++) {
            const uint32_t* b2h = &bh[nt >> 1][(nt & 1) * 2];
            const uint32_t* b2l = &bl[nt >> 1][(nt & 1) * 2];
            mma16816(acc[nt], ah, b2h);
            mma16816(acc[nt], ah, b2l);
            mma16816(acc[nt], al, b2h);
        }
    }

    int rb = m0 + wm + (lane >> 2);
    int cb = n0 + wn + (lane & 3) * 2;
    #pragma unroll
    for (int nt = 0; nt < 4; nt++) {
        int cc = cb + nt * 8;
        *reinterpret_cast<float2*>(&S[(size_t)rb * HID + cc]) =
            make_float2(acc[nt][0], acc[nt][1]);
        *reinterpret_cast<float2*>(&S[(size_t)(rb + 8) * HID + cc]) =
            make_float2(acc[nt][2], acc[nt][3]);
    }
}

#define SMEM_K192 (4 * BM * (192 * 2 + 16))   // 102400
#define SMEM_K256 (4 * BM * (256 * 2 + 16))   // 135168

// ---------------- tiny GEMM for W_out (192x3) ----------------
__global__ __launch_bounds__(256) void gemm3_kernel(const float* __restrict__ X,
                                                    const float* __restrict__ W,
                                                    float* __restrict__ S)
{
    int r = blockIdx.x * blockDim.x + threadIdx.x;
    if (r >= NN) return;
    const float* x = X + (size_t)r * HID;
    float a0 = 0.f, a1 = 0.f, a2 = 0.f;
    #pragma unroll 4
    for (int k = 0; k < HID; k++) {
        float xv = x[k];
        a0 = fmaf(xv, W[k * 3 + 0], a0);
        a1 = fmaf(xv, W[k * 3 + 1], a1);
        a2 = fmaf(xv, W[k * 3 + 2], a2);
    }
    S[r * 3 + 0] = a0; S[r * 3 + 1] = a1; S[r * 3 + 2] = a2;
}

// ---------------- fused aggregation + bias + relu + residual + bf16-split ----
__global__ __launch_bounds__(256) void agg_kernel(const float* __restrict__ S,
                                                  const float* __restrict__ bias,
                                                  const float* __restrict__ res, int res_stride,
                                                  float* __restrict__ out,
                                                  float* __restrict__ out2,
                                                  __nv_bfloat16* __restrict__ ohi,
                                                  __nv_bfloat16* __restrict__ olo,
                                                  const int* __restrict__ nidx,
                                                  const float* __restrict__ nval,
                                                  const int* __restrict__ ncnt,
                                                  int n_out, int side, int do_relu)
{
    int warp = (blockIdx.x * blockDim.x + threadIdx.x) >> 5;
    int lane = threadIdx.x & 31;
    if (warp >= NN) return;
    int cnt = ncnt[warp];
    const int* ni = nidx + (size_t)warp * MAXN;
    const float* nv = nval + (size_t)warp * MAXN;
    float acc0 = 0.f, acc1 = 0.f;
    if (side > 32) {
        float e0 = 0.f, e1 = 0.f;
        int i = 0;
        for (; i + 4 <= cnt; i += 4) {
            int   i0 = ni[i],     i1 = ni[i + 1], i2 = ni[i + 2], i3 = ni[i + 3];
            float v0 = nv[i],     v1 = nv[i + 1], v2 = nv[i + 2], v3 = nv[i + 3];
            const float* s0 = S + (size_t)i0 * n_out;
            const float* s1 = S + (size_t)i1 * n_out;
            const float* s2 = S + (size_t)i2 * n_out;
            const float* s3 = S + (size_t)i3 * n_out;
            acc0 = fmaf(v0, s0[lane], acc0);      acc1 = fmaf(v0, s0[lane + 32], acc1);
            e0   = fmaf(v1, s1[lane], e0);        e1   = fmaf(v1, s1[lane + 32], e1);
            acc0 = fmaf(v2, s2[lane], acc0);      acc1 = fmaf(v2, s2[lane + 32], acc1);
            e0   = fmaf(v3, s3[lane], e0);        e1   = fmaf(v3, s3[lane + 32], e1);
        }
        for (; i < cnt; i++) {
            const float* sr = S + (size_t)ni[i] * n_out;
            float v = nv[i];
            acc0 = fmaf(v, sr[lane], acc0);
            acc1 = fmaf(v, sr[lane + 32], acc1);
        }
        acc0 += e0; acc1 += e1;
    } else {
        for (int i = 0; i < cnt; i++) {
            if (lane < side) acc0 = fmaf(nv[i], S[(size_t)ni[i] * n_out + lane], acc0);
        }
    }
    int nj = (n_out + 31) >> 5;
    for (int j = 0; j < nj; j++) {
        int c = 32 * j + lane;
        if (c < n_out) {
            float t = (c < side) ? (j == 0 ? acc0 : acc1)
                                 : S[(size_t)warp * n_out + c];
            t += bias[c];
            if (do_relu) t = fmaxf(t, 0.f);
            if (res) t = (res[(size_t)warp * res_stride + c] + t) * 0.5f;
            size_t idx = (size_t)warp * n_out + c;
            out[idx] = t;
            if (out2) out2[idx] = t;
            if (ohi) {
                __nv_bfloat16 h = __float2bfloat16(t);
                ohi[idx] = h;
                olo[idx] = __float2bfloat16(t - __bfloat162float(h));
            }
        }
    }
}

extern "C" void kernel_launch(void* const* d_in, const int* in_sizes, int n_in,
                              void* d_out, int out_size)
{
    const float* features = (const float*)d_in[0];
    const float* adj      = (const float*)d_in[1];
    const float* W1       = (const float*)d_in[2];
    const float* b1       = (const float*)d_in[3];
    const float* W_mid    = (const float*)d_in[4];
    const float* b_mid    = (const float*)d_in[5];
    const float* W_out    = (const float*)d_in[6];
    const float* b_out    = (const float*)d_in[7];
    float* out = (float*)d_out;
    float* coords   = out;
    float* feat_out = out + NN * 3;

    float *sup, *fb, *xb, *nval;
    __nv_bfloat16 *xhi, *xlo, *whi, *wlo;
    int *nidx, *ncnt;
    cudaGetSymbolAddress((void**)&sup,  g_support);
    cudaGetSymbolAddress((void**)&fb,   g_featbuf);
    cudaGetSymbolAddress((void**)&xb,   g_xbuf);
    cudaGetSymbolAddress((void**)&xhi,  g_xhi);
    cudaGetSymbolAddress((void**)&xlo,  g_xlo);
    cudaGetSymbolAddress((void**)&whi,  g_wthi);
    cudaGetSymbolAddress((void**)&wlo,  g_wtlo);
    cudaGetSymbolAddress((void**)&nidx, g_nidx);
    cudaGetSymbolAddress((void**)&nval, g_nval);
    cudaGetSymbolAddress((void**)&ncnt, g_ncnt);

    cudaFuncSetAttribute(gemm_os<192>, cudaFuncAttributeMaxDynamicSharedMemorySize, SMEM_K192);
    cudaFuncSetAttribute(gemm_os<256>, cudaFuncAttributeMaxDynamicSharedMemorySize, SMEM_K256);

    convert_weights<<<(WT_TOTAL + 255) / 256, 256>>>(W1, W_mid, whi, wlo);
    convert_features<<<(NN * INF + 255) / 256, 256>>>(features, xhi, xlo);
    build_csr<<<NN / 8, 256>>>(adj, nidx, nval, ncnt);

    dim3 ggrid(NN / BM, HID / BN);   // 128 x 3 = 384 CTAs
    auto woff = [](int i) { return (size_t)192 * 256 + (size_t)i * 192 * 192; };

    // gc1 (K = 256)
    gemm_os<256><<<ggrid, 256, SMEM_K256>>>(xhi, xlo, whi, wlo, sup);
    agg_kernel<<<NN / 8, 256>>>(sup, b1, nullptr, 0, xb, nullptr, xhi, xlo,
                                nidx, nval, ncnt, HID, 64, 1);
    // gc2 + residual vs features[:, :192]
    gemm_os<192><<<ggrid, 256, SMEM_K192>>>(xhi, xlo, whi + woff(0), wlo + woff(0), sup);
    agg_kernel<<<NN / 8, 256>>>(sup, b_mid + 0, features, INF, fb, nullptr, xhi, xlo,
                                nidx, nval, ncnt, HID, 64, 1);

    const int pair_idx[5] = {1, 3, 5, 7, 9};
    for (int p = 0; p < 5; p++) {
        int i = pair_idx[p];
        gemm_os<192><<<ggrid, 256, SMEM_K192>>>(xhi, xlo, whi + woff(i), wlo + woff(i), sup);
        agg_kernel<<<NN / 8, 256>>>(sup, b_mid + (size_t)i * HID, nullptr, 0, xb, nullptr, xhi, xlo,
                                    nidx, nval, ncnt, HID, 64, 1);
        gemm_os<192><<<ggrid, 256, SMEM_K192>>>(xhi, xlo, whi + woff(i + 1), wlo + woff(i + 1), sup);
        agg_kernel<<<NN / 8, 256>>>(sup, b_mid + (size_t)(i + 1) * HID, fb, HID, fb, nullptr, xhi, xlo,
                                    nidx, nval, ncnt, HID, 64, 1);
    }

    // gc13 (+ residual); writes feat to output region too
    gemm_os<192><<<ggrid, 256, SMEM_K192>>>(xhi, xlo, whi + woff(11), wlo + woff(11), sup);
    agg_kernel<<<NN / 8, 256>>>(sup, b_mid + (size_t)11 * HID, fb, HID, fb, feat_out, nullptr, nullptr,
                                nidx, nval, ncnt, HID, 64, 1);

    // gc14: coords, side_len = 2, no relu
    gemm3_kernel<<<NN / 256, 256>>>(fb, W_out, sup);
    agg_kernel<<<NN / 8, 256>>>(sup, b_out, nullptr, 0, coords, nullptr, nullptr, nullptr,
                                nidx, nval, ncnt, 3, 2, 0);
}